// round 16
// baseline (speedup 1.0000x reference)
#include <cuda_runtime.h>
#include <cuda_fp16.h>
#include <cstdint>

#define E    512
#define HD   256
#define MTXT 2048
#define MVID 8192
#define NSPLIT 8
#define KSPL  1024

#define BM 128
#define BN 128
#define BK 64        // k-halves per stage (4 x k16 mma steps)
#define HSTR 72      // smem row stride in halves = 144B (ldmatrix conflict-free)
#define STAGEH ((BM + BN) * HSTR)    // 18432 halves
#define STAGEB (STAGEH * 2)          // 36864 B
#define NSTAGE 3
#define SMEM_BYTES (NSTAGE * STAGEB) // 110592 B

// ---------------- device scratch ----------------
__device__ __half g_th[(long long)MTXT * E];
__device__ __half g_vh[(long long)MVID * E];
__device__ __half g_Wqh[E * E], g_Wkh[E * E], g_Wvh[E * E], g_Woh[E * E];
__device__ __half g_Qh[(long long)MTXT * E];
__device__ __half g_Kh[(long long)MVID * E];
__device__ __half g_Vth[2ll * HD * MVID];
__device__ __half g_Wth[2ll * MTXT * MVID];
__device__ float  g_part[(long long)NSPLIT * MTXT * E];
__device__ __half g_Ah[(long long)MTXT * E];

__device__ __forceinline__ uint32_t smem_u32(const void* p) {
    uint32_t a;
    asm("{ .reg .u64 t; cvta.to.shared.u64 t, %1; cvt.u32.u64 %0, t; }" : "=r"(a) : "l"(p));
    return a;
}
__device__ __forceinline__ uint32_t packh2(float a, float b) {
    __half2 h = __floats2half2_rn(a, b);
    return *reinterpret_cast<uint32_t*>(&h);
}
__device__ __forceinline__ void cpa16(uint32_t d, const void* g) {
    asm volatile("cp.async.cg.shared.global [%0], [%1], 16;" :: "r"(d), "l"(g));
}
#define CP_COMMIT() asm volatile("cp.async.commit_group;" ::: "memory")
#define CP_WAIT1()  asm volatile("cp.async.wait_group 1;" ::: "memory")
#define CP_WAIT0()  asm volatile("cp.async.wait_group 0;" ::: "memory")

__device__ __forceinline__ void mma_f16(float* c, const uint32_t* a,
                                        uint32_t b0, uint32_t b1) {
    asm volatile(
        "mma.sync.aligned.m16n8k16.row.col.f32.f16.f16.f32 "
        "{%0,%1,%2,%3}, {%4,%5,%6,%7}, {%8,%9}, {%0,%1,%2,%3};"
        : "+f"(c[0]), "+f"(c[1]), "+f"(c[2]), "+f"(c[3])
        : "r"(a[0]), "r"(a[1]), "r"(a[2]), "r"(a[3]), "r"(b0), "r"(b1));
}
__device__ __forceinline__ void ldsm_x4(uint32_t* r, uint32_t addr) {
    asm volatile("ldmatrix.sync.aligned.m8n8.x4.shared.b16 {%0,%1,%2,%3}, [%4];"
        : "=r"(r[0]), "=r"(r[1]), "=r"(r[2]), "=r"(r[3]) : "r"(addr));
}

// ---------------------------------------------------------------------------
// fp16 mma.sync GEMM (fp32 accum), cp.async 3-stage pipeline, BK=64.
// 128 threads (4 warps), block tile 128x128, warp tile 64x64.
// D[m,n] = sum_k A[m,k] * B[n,k]   (both K-major, fp16)
// epi: 0 = bias+store fp32 (final)      1 = Vt transpose store (half)
//      3 = attn scatter fp32 (reshape)  4 = bias+store half (Q/K)
//      5 = fused softmax-over-frames -> Wt[h][bt][av] (half, /16, /128)
// mode 1 = merged QKV launch: z selects {Q,K,V}, pointers from globals.
// ---------------------------------------------------------------------------
__global__ __launch_bounds__(128, 2) void gemm_h(
    const __half* __restrict__ Ap, int lda, long long aH, long long aS,
    const __half* __restrict__ Bp, int ldb, long long bH, long long bS,
    const float* __restrict__ biasp, void* __restrict__ Dvp,
    int K, int nsplit, long long pStride,
    int epip, int ldd, long long dH, float scale,
    int mode, const float* __restrict__ bias2, const float* __restrict__ bias3)
{
    extern __shared__ __half smem[];

    const __half* A = Ap;
    const __half* B = Bp;
    const float* bias = biasp;
    void* Dv = Dvp;
    int epi = epip;

    int zh = blockIdx.z / nsplit;
    int zs = blockIdx.z % nsplit;

    if (mode == 1) {
        zh = 0; zs = 0;
        if (blockIdx.z == 0) {
            if (blockIdx.y >= 16) return;
            A = g_th;  B = g_Wqh; Dv = g_Qh;  epi = 4;    // bias = bq (passed)
        } else if (blockIdx.z == 1) {
            A = g_vh;  B = g_Wkh; Dv = g_Kh;  epi = 4; bias = bias2;
        } else {
            A = g_vh;  B = g_Wvh; Dv = g_Vth; epi = 1; bias = bias3;
        }
    }

    const int tid  = threadIdx.x;
    const int warp = tid >> 5;
    const int lane = tid & 31;
    const int gid  = lane >> 2;
    const int tig  = lane & 3;
    const int wm   = warp & 1;     // 2 m-groups of 64
    const int wn   = warp >> 1;    // 2 n-groups of 64

    const int m0 = blockIdx.y * BM;
    const int n0 = blockIdx.x * BN;
    const __half* Ab = A + zh * aH + zs * aS;
    const __half* Bb = B + zh * bH + zs * bS;

    float acc[4][8][4];
#pragma unroll
    for (int i = 0; i < 4; i++)
#pragma unroll
        for (int j = 0; j < 8; j++)
#pragma unroll
            for (int c = 0; c < 4; c++) acc[i][j][c] = 0.0f;

    // ---- loader: one A row + one B row per thread, 8+8 cp.async 16B ----
    const uint32_t baseU = smem_u32(smem);
    const char* gA = (const char*)(Ab + (long long)(m0 + tid) * lda);
    const char* gB = (const char*)(Bb + (long long)(n0 + tid) * ldb);
    const uint32_t sA = baseU + (uint32_t)(tid * 144);
    const uint32_t sB = baseU + (uint32_t)(BM * 144 + tid * 144);

    auto issue = [&](int s, int bu) {
        const int kB = s * (BK * 2);          // 128 bytes per stage
        const uint32_t off = (uint32_t)(bu * STAGEB);
#pragma unroll
        for (int i = 0; i < 8; i++)
            cpa16(sA + off + (uint32_t)(i * 16), gA + kB + i * 16);
#pragma unroll
        for (int i = 0; i < 8; i++)
            cpa16(sB + off + (uint32_t)(i * 16), gB + kB + i * 16);
        CP_COMMIT();
    };

    // ---- fragment addresses ----
    const int lrF = lane & 15;
    const int lcF = (lane >> 4) * 8;
    uint32_t aAddr[4], bAddr[4];
#pragma unroll
    for (int mt = 0; mt < 4; mt++)
        aAddr[mt] = baseU + (uint32_t)(((wm * 64 + mt * 16 + lrF) * HSTR + lcF) * 2);
#pragma unroll
    for (int p = 0; p < 4; p++)
        bAddr[p] = baseU + (uint32_t)((BM * HSTR + (wn * 64 + p * 16 + lrF) * HSTR + lcF) * 2);

    auto compute = [&](int st) {
        const uint32_t off = (uint32_t)(st * STAGEB);
#pragma unroll
        for (int ks = 0; ks < 4; ks++) {
            const uint32_t kb = (uint32_t)(ks * 32) + off;
            uint32_t af[4][4], bq[4][4];
#pragma unroll
            for (int mt = 0; mt < 4; mt++) ldsm_x4(af[mt], aAddr[mt] + kb);
#pragma unroll
            for (int p = 0; p < 4; p++)  ldsm_x4(bq[p], bAddr[p] + kb);
#pragma unroll
            for (int mt = 0; mt < 4; mt++)
#pragma unroll
                for (int nt = 0; nt < 8; nt++)
                    mma_f16(acc[mt][nt], af[mt],
                            bq[nt >> 1][nt & 1], bq[nt >> 1][2 + (nt & 1)]);
        }
    };

    const int S = K / BK;
    issue(0, 0);
    if (S > 1) issue(1, 1);
    int st = 0;
    for (int s = 0; s < S; s++) {
        if (s + 1 < S) CP_WAIT1(); else CP_WAIT0();
        __syncthreads();
        if (s + 2 < S) issue(s + 2, (st + 2) % NSTAGE);
        compute(st);
        st = (st + 1) % NSTAGE;
    }

    // ---------------- epilogues ----------------
    if (epi == 5) {
        // softmax over the 64 frame-rows of this thread's wm-half (one video),
        // transposed store to Wt[h][bt][av], half, with /16 and /128 folded in.
#pragma unroll
        for (int nt = 0; nt < 8; nt++) {
#pragma unroll
            for (int p = 0; p < 2; p++) {
                float m = -1e30f;
#pragma unroll
                for (int mt = 0; mt < 4; mt++)
                    m = fmaxf(m, fmaxf(acc[mt][nt][p], acc[mt][nt][p + 2]));
                m = fmaxf(m, __shfl_xor_sync(0xffffffffu, m, 4));
                m = fmaxf(m, __shfl_xor_sync(0xffffffffu, m, 8));
                m = fmaxf(m, __shfl_xor_sync(0xffffffffu, m, 16));
                float sum = 0.0f;
#pragma unroll
                for (int mt = 0; mt < 4; mt++) {
                    float e0 = __expf((acc[mt][nt][p]     - m) * 0.0625f);
                    float e1 = __expf((acc[mt][nt][p + 2] - m) * 0.0625f);
                    acc[mt][nt][p]     = e0;
                    acc[mt][nt][p + 2] = e1;
                    sum += e0 + e1;
                }
                sum += __shfl_xor_sync(0xffffffffu, sum, 4);
                sum += __shfl_xor_sync(0xffffffffu, sum, 8);
                sum += __shfl_xor_sync(0xffffffffu, sum, 16);
                const float inv = 1.0f / (128.0f * sum);
                const int bt = n0 + wn * 64 + nt * 8 + 2 * tig + p;
                const int rb2 = m0 + wm * 64 + gid;
                __half* Wc = (__half*)Dv + (long long)zh * dH + (long long)bt * MVID;
#pragma unroll
                for (int mt = 0; mt < 4; mt++) {
                    Wc[rb2 + mt * 16    ] = __float2half_rn(acc[mt][nt][p]     * inv);
                    Wc[rb2 + mt * 16 + 8] = __float2half_rn(acc[mt][nt][p + 2] * inv);
                }
            }
        }
        return;
    }

#pragma unroll
    for (int mt = 0; mt < 4; mt++) {
#pragma unroll
        for (int nt = 0; nt < 8; nt++) {
            const int r0 = m0 + wm * 64 + mt * 16 + gid;
            const int cN = n0 + wn * 64 + nt * 8 + 2 * tig;
#pragma unroll
            for (int half = 0; half < 2; half++) {
                const int r = r0 + half * 8;
                float x = acc[mt][nt][half * 2 + 0];
                float y = acc[mt][nt][half * 2 + 1];
                if (epi == 0) {
                    float2 o = make_float2(x * scale + bias[cN],
                                           y * scale + bias[cN + 1]);
                    *(float2*)&((float*)Dv)[dH * zh + (long long)r * ldd + cN] = o;
                } else if (epi == 4) {
                    __half2 h = __floats2half2_rn(x * scale + bias[cN],
                                                  y * scale + bias[cN + 1]);
                    *(__half2*)&((__half*)Dv)[dH * zh + (long long)r * ldd + cN] = h;
                } else if (epi == 1) {
                    ((__half*)Dv)[(long long)(cN    ) * MVID + r] = __float2half_rn(x);
                    ((__half*)Dv)[(long long)(cN + 1) * MVID + r] = __float2half_rn(y);
                } else {
                    long long addr = (long long)zs * pStride
                                   + (long long)(r >> 5) * 16384
                                   + (long long)zh * 8192
                                   + (r & 31) * 256 + cN;
                    *(float2*)&((float*)Dv)[addr] = make_float2(x, y);
                }
            }
        }
    }
}

// ---------------------------------------------------------------------------
// Merged fp32 -> fp16 converter for all six inputs (8 elems per thread-task)
// ---------------------------------------------------------------------------
#define N8_T  (MTXT * E / 8)          // 131072
#define N8_V  (MVID * E / 8)          // 524288
#define N8_W  (E * E / 8)             // 32768
#define N8_ALL (N8_T + N8_V + 4 * N8_W)

__global__ void cvt_all(const float* __restrict__ t, const float* __restrict__ v,
                        const float* __restrict__ wq, const float* __restrict__ wk,
                        const float* __restrict__ wv, const float* __restrict__ wo,
                        __half* __restrict__ dt, __half* __restrict__ dvh,
                        __half* __restrict__ dwq, __half* __restrict__ dwk,
                        __half* __restrict__ dwv, __half* __restrict__ dwo)
{
    int i = blockIdx.x * blockDim.x + threadIdx.x;
    if (i >= N8_ALL) return;
    const float* s; __half* d; int off;
    if (i < N8_V) { s = v; d = dvh; off = i; }
    else if (i < N8_V + N8_T) { s = t; d = dt; off = i - N8_V; }
    else {
        int j = i - N8_V - N8_T;
        int w = j / N8_W; off = j % N8_W;
        s = (w == 0) ? wq : (w == 1) ? wk : (w == 2) ? wv : wo;
        d = (w == 0) ? dwq : (w == 1) ? dwk : (w == 2) ? dwv : dwo;
    }
    const float4* sp = (const float4*)s + 2 * (long long)off;
    float4 a = sp[0], b = sp[1];
    uint4 o;
    o.x = packh2(a.x, a.y); o.y = packh2(a.z, a.w);
    o.z = packh2(b.x, b.y); o.w = packh2(b.z, b.w);
    *((uint4*)d + off) = o;
}

// Sum the 8 split-K fp32 partials and convert to fp16 (4 elems/thread)
__global__ void sum8cvt(const float* __restrict__ p, __half* __restrict__ d, int n4)
{
    int i = blockIdx.x * blockDim.x + threadIdx.x;
    if (i < n4) {
        const long long st = (long long)MTXT * E / 4;
        float4 v = *((const float4*)p + i);
#pragma unroll
        for (int k = 1; k < NSPLIT; k++) {
            float4 b = *((const float4*)p + (long long)k * st + i);
            v.x += b.x; v.y += b.y; v.z += b.z; v.w += b.w;
        }
        uint2 o;
        o.x = packh2(v.x, v.y); o.y = packh2(v.z, v.w);
        *((uint2*)d + i) = o;
    }
}

// ---------------------------------------------------------------------------
extern "C" void kernel_launch(void* const* d_in, const int* in_sizes, int n_in,
                              void* d_out, int out_size)
{
    const float* text  = (const float*)d_in[0];
    const float* video = (const float*)d_in[1];
    const float* Wq = (const float*)d_in[2];
    const float* bq = (const float*)d_in[3];
    const float* Wk = (const float*)d_in[4];
    const float* bk = (const float*)d_in[5];
    const float* Wv = (const float*)d_in[6];
    const float* bv = (const float*)d_in[7];
    const float* Wo = (const float*)d_in[8];
    const float* bo = (const float*)d_in[9];
    float* out = (float*)d_out;

    __half *thp, *vhp, *Wqh, *Wkh, *Wvh, *Woh, *Qp, *Kp, *Vtp, *Wtp, *Ahp;
    float* Pp;
    cudaGetSymbolAddress((void**)&thp, g_th);
    cudaGetSymbolAddress((void**)&vhp, g_vh);
    cudaGetSymbolAddress((void**)&Wqh, g_Wqh);
    cudaGetSymbolAddress((void**)&Wkh, g_Wkh);
    cudaGetSymbolAddress((void**)&Wvh, g_Wvh);
    cudaGetSymbolAddress((void**)&Woh, g_Woh);
    cudaGetSymbolAddress((void**)&Qp,  g_Qh);
    cudaGetSymbolAddress((void**)&Kp,  g_Kh);
    cudaGetSymbolAddress((void**)&Vtp, g_Vth);
    cudaGetSymbolAddress((void**)&Wtp, g_Wth);
    cudaGetSymbolAddress((void**)&Pp,  g_part);
    cudaGetSymbolAddress((void**)&Ahp, g_Ah);

    cudaFuncSetAttribute(gemm_h,
                         cudaFuncAttributeMaxDynamicSharedMemorySize, SMEM_BYTES);

    dim3 t(128);

    // ---- merged input conversion to fp16 ----
    cvt_all<<<(N8_ALL + 255) / 256, 256>>>(text, video, Wq, Wk, Wv, Wo,
                                           thp, vhp, Wqh, Wkh, Wvh, Woh);

    // ---- merged Q/K/V projections (mode 1): z = {Q, K, V} ----
    gemm_h<<<dim3(4, 64, 3), t, SMEM_BYTES>>>(nullptr, 512, 0, 0, nullptr, 512, 0, 0,
        bq, nullptr, 512, 1, 0, 4, 512, 0, 1.0f, 1, bk, bv);

    // ---- logits + fused softmax -> Wt[h][bt][av] ----
    gemm_h<<<dim3(16, 64, 2), t, SMEM_BYTES>>>(Kp, 512, 256, 0, Qp, 512, 256, 0,
        nullptr, Wtp, 256, 1, 0, 5, 0, (long long)MTXT * MVID, 1.0f, 0, nullptr, nullptr);

    // ---- attention: split-K x8, fp32 partials ----
    gemm_h<<<dim3(2, 16, 2 * NSPLIT), t, SMEM_BYTES>>>(Wtp, MVID,
        (long long)MTXT * MVID, KSPL,
        Vtp, MVID, (long long)HD * MVID, KSPL,
        nullptr, Pp, KSPL, NSPLIT, (long long)MTXT * E, 3, 0, 0, 1.0f, 0, nullptr, nullptr);

    // ---- sum partials + convert ----
    sum8cvt<<<1024, 256>>>(Pp, Ahp, MTXT * E / 4);

    // ---- output projection ----
    gemm_h<<<dim3(4, 16, 1), t, SMEM_BYTES>>>(Ahp, 512, 0, 0, Woh, 512, 0, 0,
        bo, out, 512, 1, 0, 0, 512, 0, 1.0f, 0, nullptr, nullptr);
}

// round 17
// speedup vs baseline: 1.3805x; 1.3805x over previous
#include <cuda_runtime.h>
#include <cuda_fp16.h>
#include <cstdint>

#define E    512
#define HD   256
#define MTXT 2048
#define MVID 8192
#define NSPLIT 4
#define KSPL  2048

#define BM 128
#define BN 128
#define BK 32        // k-halves per stage (2 x k16 mma steps)
#define HSTR 40      // smem row stride in halves (ldmatrix conflict-free)
#define STAGEH ((BM + BN) * HSTR)    // 10240 halves
#define STAGEB (STAGEH * 2)          // 20480 B
#define NSTAGE 3
#define SMEM_BYTES (NSTAGE * STAGEB) // 61440 B

// ---------------- device scratch ----------------
__device__ __half g_th[(long long)MTXT * E];
__device__ __half g_vh[(long long)MVID * E];
__device__ __half g_Wqh[E * E], g_Wkh[E * E], g_Wvh[E * E], g_Woh[E * E];
__device__ __half g_Qh[(long long)MTXT * E];
__device__ __half g_Kh[(long long)MVID * E];
__device__ __half g_Vth[2ll * HD * MVID];
__device__ __half g_Wth[2ll * MTXT * MVID];
__device__ float  g_part[(long long)NSPLIT * MTXT * E];
__device__ __half g_Ah[(long long)MTXT * E];

__device__ __forceinline__ uint32_t smem_u32(const void* p) {
    uint32_t a;
    asm("{ .reg .u64 t; cvta.to.shared.u64 t, %1; cvt.u32.u64 %0, t; }" : "=r"(a) : "l"(p));
    return a;
}
__device__ __forceinline__ uint32_t packh2(float a, float b) {
    __half2 h = __floats2half2_rn(a, b);
    return *reinterpret_cast<uint32_t*>(&h);
}
__device__ __forceinline__ void cpa16(uint32_t d, const void* g) {
    asm volatile("cp.async.cg.shared.global [%0], [%1], 16;" :: "r"(d), "l"(g));
}
#define CP_COMMIT() asm volatile("cp.async.commit_group;" ::: "memory")
#define CP_WAIT1()  asm volatile("cp.async.wait_group 1;" ::: "memory")
#define CP_WAIT0()  asm volatile("cp.async.wait_group 0;" ::: "memory")

__device__ __forceinline__ void mma_f16(float* c, const uint32_t* a,
                                        uint32_t b0, uint32_t b1) {
    asm volatile(
        "mma.sync.aligned.m16n8k16.row.col.f32.f16.f16.f32 "
        "{%0,%1,%2,%3}, {%4,%5,%6,%7}, {%8,%9}, {%0,%1,%2,%3};"
        : "+f"(c[0]), "+f"(c[1]), "+f"(c[2]), "+f"(c[3])
        : "r"(a[0]), "r"(a[1]), "r"(a[2]), "r"(a[3]), "r"(b0), "r"(b1));
}
__device__ __forceinline__ void ldsm_x4(uint32_t* r, uint32_t addr) {
    asm volatile("ldmatrix.sync.aligned.m8n8.x4.shared.b16 {%0,%1,%2,%3}, [%4];"
        : "=r"(r[0]), "=r"(r[1]), "=r"(r[2]), "=r"(r[3]) : "r"(addr));
}

// ---------------------------------------------------------------------------
// fp16 mma.sync GEMM (fp32 accum), cp.async 3-stage pipeline, BK=32.
// 128 threads (4 warps), block tile 128x128, warp tile 64x64.
// D[m,n] = sum_k A[m,k] * B[n,k]   (both K-major, fp16)
// epi: 0 = bias+store fp32 (final)      1 = Vt transpose store (half)
//      3 = attn scatter fp32 (reshape)  4 = bias+store half (Q/K)
//      5 = fused softmax-over-frames -> Wt[h][bt][av] (half, /16, /128)
// mode 1 = merged QKV launch: z selects {Q,K,V}, pointers from globals.
// ---------------------------------------------------------------------------
__global__ __launch_bounds__(128, 2) void gemm_h(
    const __half* __restrict__ Ap, int lda, long long aH, long long aS,
    const __half* __restrict__ Bp, int ldb, long long bH, long long bS,
    const float* __restrict__ biasp, void* __restrict__ Dvp,
    int K, int nsplit, long long pStride,
    int epip, int ldd, long long dH, float scale,
    int mode, const float* __restrict__ bias2, const float* __restrict__ bias3)
{
    extern __shared__ __half smem[];

    const __half* A = Ap;
    const __half* B = Bp;
    const float* bias = biasp;
    void* Dv = Dvp;
    int epi = epip;

    int zh = blockIdx.z / nsplit;
    int zs = blockIdx.z % nsplit;

    if (mode == 1) {
        zh = 0; zs = 0;
        if (blockIdx.z == 0) {
            if (blockIdx.y >= 16) return;
            A = g_th;  B = g_Wqh; Dv = g_Qh;  epi = 4;    // bias = bq (passed)
        } else if (blockIdx.z == 1) {
            A = g_vh;  B = g_Wkh; Dv = g_Kh;  epi = 4; bias = bias2;
        } else {
            A = g_vh;  B = g_Wvh; Dv = g_Vth; epi = 1; bias = bias3;
        }
    }

    const int tid  = threadIdx.x;
    const int warp = tid >> 5;
    const int lane = tid & 31;
    const int gid  = lane >> 2;
    const int tig  = lane & 3;
    const int wm   = warp & 1;     // 2 m-groups of 64
    const int wn   = warp >> 1;    // 2 n-groups of 64

    const int m0 = blockIdx.y * BM;
    const int n0 = blockIdx.x * BN;
    const __half* Ab = A + zh * aH + zs * aS;
    const __half* Bb = B + zh * bH + zs * bS;

    float acc[4][8][4];
#pragma unroll
    for (int i = 0; i < 4; i++)
#pragma unroll
        for (int j = 0; j < 8; j++)
#pragma unroll
            for (int c = 0; c < 4; c++) acc[i][j][c] = 0.0f;

    // ---- loader: 8 cp.async 16B per thread per stage ----
    const int lrow = tid >> 2;            // 0..31
    const int lch  = (tid & 3) * 16;      // byte chunk in row
    const uint32_t baseU = smem_u32(smem);
    const char* gA = (const char*)(Ab + (long long)(m0 + lrow) * lda) + lch;
    const char* gB = (const char*)(Bb + (long long)(n0 + lrow) * ldb) + lch;
    const long long aStep = (long long)lda * 32 * 2;   // 32 rows in bytes
    const long long bStep = (long long)ldb * 32 * 2;
    const uint32_t sA = baseU + (uint32_t)(lrow * 80 + lch);
    const uint32_t sB = baseU + (uint32_t)(BM * 80 + lrow * 80 + lch);

    auto issue = [&](int s, int bu) {
        const int kB = s * (BK * 2);          // 64 bytes per stage
        const uint32_t off = (uint32_t)(bu * STAGEB);
#pragma unroll
        for (int i = 0; i < 4; i++)
            cpa16(sA + off + (uint32_t)(i * 32 * 80), gA + i * aStep + kB);
#pragma unroll
        for (int i = 0; i < 4; i++)
            cpa16(sB + off + (uint32_t)(i * 32 * 80), gB + i * bStep + kB);
        CP_COMMIT();
    };

    // ---- fragment addresses ----
    const int lrF = lane & 15;
    const int lcF = (lane >> 4) * 8;
    uint32_t aAddr[4], bAddr[4];
#pragma unroll
    for (int mt = 0; mt < 4; mt++)
        aAddr[mt] = baseU + (uint32_t)(((wm * 64 + mt * 16 + lrF) * HSTR + lcF) * 2);
#pragma unroll
    for (int p = 0; p < 4; p++)
        bAddr[p] = baseU + (uint32_t)((BM * HSTR + (wn * 64 + p * 16 + lrF) * HSTR + lcF) * 2);

    auto compute = [&](int st) {
        const uint32_t off = (uint32_t)(st * STAGEB);
#pragma unroll
        for (int ks = 0; ks < 2; ks++) {
            const uint32_t kb = (uint32_t)(ks * 32) + off;
            uint32_t af[4][4], bq[4][4];
#pragma unroll
            for (int mt = 0; mt < 4; mt++) ldsm_x4(af[mt], aAddr[mt] + kb);
#pragma unroll
            for (int p = 0; p < 4; p++)  ldsm_x4(bq[p], bAddr[p] + kb);
#pragma unroll
            for (int mt = 0; mt < 4; mt++)
#pragma unroll
                for (int nt = 0; nt < 8; nt++)
                    mma_f16(acc[mt][nt], af[mt],
                            bq[nt >> 1][nt & 1], bq[nt >> 1][2 + (nt & 1)]);
        }
    };

    const int S = K / BK;
    issue(0, 0);
    if (S > 1) issue(1, 1);
    int st = 0;
    for (int s = 0; s < S; s++) {
        if (s + 1 < S) CP_WAIT1(); else CP_WAIT0();
        __syncthreads();
        if (s + 2 < S) issue(s + 2, (st + 2) % NSTAGE);
        compute(st);
        st = (st + 1) % NSTAGE;
    }

    // ---------------- epilogues ----------------
    if (epi == 5) {
        // softmax over the 64 frame-rows of this thread's wm-half (one video),
        // transposed store to Wt[h][bt][av], half, with /16 and /128 folded in.
#pragma unroll
        for (int nt = 0; nt < 8; nt++) {
#pragma unroll
            for (int p = 0; p < 2; p++) {
                float m = -1e30f;
#pragma unroll
                for (int mt = 0; mt < 4; mt++)
                    m = fmaxf(m, fmaxf(acc[mt][nt][p], acc[mt][nt][p + 2]));
                m = fmaxf(m, __shfl_xor_sync(0xffffffffu, m, 4));
                m = fmaxf(m, __shfl_xor_sync(0xffffffffu, m, 8));
                m = fmaxf(m, __shfl_xor_sync(0xffffffffu, m, 16));
                float sum = 0.0f;
#pragma unroll
                for (int mt = 0; mt < 4; mt++) {
                    float e0 = __expf((acc[mt][nt][p]     - m) * 0.0625f);
                    float e1 = __expf((acc[mt][nt][p + 2] - m) * 0.0625f);
                    acc[mt][nt][p]     = e0;
                    acc[mt][nt][p + 2] = e1;
                    sum += e0 + e1;
                }
                sum += __shfl_xor_sync(0xffffffffu, sum, 4);
                sum += __shfl_xor_sync(0xffffffffu, sum, 8);
                sum += __shfl_xor_sync(0xffffffffu, sum, 16);
                const float inv = 1.0f / (128.0f * sum);
                const int bt = n0 + wn * 64 + nt * 8 + 2 * tig + p;
                const int rb2 = m0 + wm * 64 + gid;
                __half* Wc = (__half*)Dv + (long long)zh * dH + (long long)bt * MVID;
#pragma unroll
                for (int mt = 0; mt < 4; mt++) {
                    Wc[rb2 + mt * 16    ] = __float2half_rn(acc[mt][nt][p]     * inv);
                    Wc[rb2 + mt * 16 + 8] = __float2half_rn(acc[mt][nt][p + 2] * inv);
                }
            }
        }
        return;
    }

#pragma unroll
    for (int mt = 0; mt < 4; mt++) {
#pragma unroll
        for (int nt = 0; nt < 8; nt++) {
            const int r0 = m0 + wm * 64 + mt * 16 + gid;
            const int cN = n0 + wn * 64 + nt * 8 + 2 * tig;
#pragma unroll
            for (int half = 0; half < 2; half++) {
                const int r = r0 + half * 8;
                float x = acc[mt][nt][half * 2 + 0];
                float y = acc[mt][nt][half * 2 + 1];
                if (epi == 0) {
                    float2 o = make_float2(x * scale + bias[cN],
                                           y * scale + bias[cN + 1]);
                    *(float2*)&((float*)Dv)[dH * zh + (long long)r * ldd + cN] = o;
                } else if (epi == 4) {
                    __half2 h = __floats2half2_rn(x * scale + bias[cN],
                                                  y * scale + bias[cN + 1]);
                    *(__half2*)&((__half*)Dv)[dH * zh + (long long)r * ldd + cN] = h;
                } else if (epi == 1) {
                    ((__half*)Dv)[(long long)(cN    ) * MVID + r] = __float2half_rn(x);
                    ((__half*)Dv)[(long long)(cN + 1) * MVID + r] = __float2half_rn(y);
                } else {
                    long long addr = (long long)zs * pStride
                                   + (long long)(r >> 5) * 16384
                                   + (long long)zh * 8192
                                   + (r & 31) * 256 + cN;
                    *(float2*)&((float*)Dv)[addr] = make_float2(x, y);
                }
            }
        }
    }
}

// ---------------------------------------------------------------------------
// Merged fp32 -> fp16 converter for all six inputs (8 elems per thread-task)
// ---------------------------------------------------------------------------
#define N8_T  (MTXT * E / 8)          // 131072
#define N8_V  (MVID * E / 8)          // 524288
#define N8_W  (E * E / 8)             // 32768
#define N8_ALL (N8_T + N8_V + 4 * N8_W)

__global__ void cvt_all(const float* __restrict__ t, const float* __restrict__ v,
                        const float* __restrict__ wq, const float* __restrict__ wk,
                        const float* __restrict__ wv, const float* __restrict__ wo,
                        __half* __restrict__ dt, __half* __restrict__ dvh,
                        __half* __restrict__ dwq, __half* __restrict__ dwk,
                        __half* __restrict__ dwv, __half* __restrict__ dwo)
{
    int i = blockIdx.x * blockDim.x + threadIdx.x;
    if (i >= N8_ALL) return;
    const float* s; __half* d; int off;
    if (i < N8_V) { s = v; d = dvh; off = i; }
    else if (i < N8_V + N8_T) { s = t; d = dt; off = i - N8_V; }
    else {
        int j = i - N8_V - N8_T;
        int w = j / N8_W; off = j % N8_W;
        s = (w == 0) ? wq : (w == 1) ? wk : (w == 2) ? wv : wo;
        d = (w == 0) ? dwq : (w == 1) ? dwk : (w == 2) ? dwv : dwo;
    }
    const float4* sp = (const float4*)s + 2 * (long long)off;
    float4 a = sp[0], b = sp[1];
    uint4 o;
    o.x = packh2(a.x, a.y); o.y = packh2(a.z, a.w);
    o.z = packh2(b.x, b.y); o.w = packh2(b.z, b.w);
    *((uint4*)d + off) = o;
}

// Sum the 4 split-K fp32 partials and convert to fp16 (4 elems/thread)
__global__ void sum4cvt(const float* __restrict__ p, __half* __restrict__ d, int n4)
{
    int i = blockIdx.x * blockDim.x + threadIdx.x;
    if (i < n4) {
        const long long st = (long long)MTXT * E / 4;
        float4 v = *((const float4*)p + i);
#pragma unroll
        for (int k = 1; k < NSPLIT; k++) {
            float4 b = *((const float4*)p + (long long)k * st + i);
            v.x += b.x; v.y += b.y; v.z += b.z; v.w += b.w;
        }
        uint2 o;
        o.x = packh2(v.x, v.y); o.y = packh2(v.z, v.w);
        *((uint2*)d + i) = o;
    }
}

// ---------------------------------------------------------------------------
extern "C" void kernel_launch(void* const* d_in, const int* in_sizes, int n_in,
                              void* d_out, int out_size)
{
    const float* text  = (const float*)d_in[0];
    const float* video = (const float*)d_in[1];
    const float* Wq = (const float*)d_in[2];
    const float* bq = (const float*)d_in[3];
    const float* Wk = (const float*)d_in[4];
    const float* bk = (const float*)d_in[5];
    const float* Wv = (const float*)d_in[6];
    const float* bv = (const float*)d_in[7];
    const float* Wo = (const float*)d_in[8];
    const float* bo = (const float*)d_in[9];
    float* out = (float*)d_out;

    __half *thp, *vhp, *Wqh, *Wkh, *Wvh, *Woh, *Qp, *Kp, *Vtp, *Wtp, *Ahp;
    float* Pp;
    cudaGetSymbolAddress((void**)&thp, g_th);
    cudaGetSymbolAddress((void**)&vhp, g_vh);
    cudaGetSymbolAddress((void**)&Wqh, g_Wqh);
    cudaGetSymbolAddress((void**)&Wkh, g_Wkh);
    cudaGetSymbolAddress((void**)&Wvh, g_Wvh);
    cudaGetSymbolAddress((void**)&Woh, g_Woh);
    cudaGetSymbolAddress((void**)&Qp,  g_Qh);
    cudaGetSymbolAddress((void**)&Kp,  g_Kh);
    cudaGetSymbolAddress((void**)&Vtp, g_Vth);
    cudaGetSymbolAddress((void**)&Wtp, g_Wth);
    cudaGetSymbolAddress((void**)&Pp,  g_part);
    cudaGetSymbolAddress((void**)&Ahp, g_Ah);

    cudaFuncSetAttribute(gemm_h,
                         cudaFuncAttributeMaxDynamicSharedMemorySize, SMEM_BYTES);

    dim3 t(128);

    // ---- merged input conversion to fp16 ----
    cvt_all<<<(N8_ALL + 255) / 256, 256>>>(text, video, Wq, Wk, Wv, Wo,
                                           thp, vhp, Wqh, Wkh, Wvh, Woh);

    // ---- merged Q/K/V projections (mode 1): z = {Q, K, V} ----
    gemm_h<<<dim3(4, 64, 3), t, SMEM_BYTES>>>(nullptr, 512, 0, 0, nullptr, 512, 0, 0,
        bq, nullptr, 512, 1, 0, 4, 512, 0, 1.0f, 1, bk, bv);

    // ---- logits + fused softmax -> Wt[h][bt][av] ----
    gemm_h<<<dim3(16, 64, 2), t, SMEM_BYTES>>>(Kp, 512, 256, 0, Qp, 512, 256, 0,
        nullptr, Wtp, 256, 1, 0, 5, 0, (long long)MTXT * MVID, 1.0f, 0, nullptr, nullptr);

    // ---- attention: split-K x4, fp32 partials ----
    gemm_h<<<dim3(2, 16, 2 * NSPLIT), t, SMEM_BYTES>>>(Wtp, MVID,
        (long long)MTXT * MVID, KSPL,
        Vtp, MVID, (long long)HD * MVID, KSPL,
        nullptr, Pp, KSPL, NSPLIT, (long long)MTXT * E, 3, 0, 0, 1.0f, 0, nullptr, nullptr);

    // ---- sum partials + convert ----
    sum4cvt<<<1024, 256>>>(Pp, Ahp, MTXT * E / 4);

    // ---- output projection ----
    gemm_h<<<dim3(4, 16, 1), t, SMEM_BYTES>>>(Ahp, 512, 0, 0, Woh, 512, 0, 0,
        bo, out, 512, 1, 0, 0, 512, 0, 1.0f, 0, nullptr, nullptr);
}